// round 12
// baseline (speedup 1.0000x reference)
#include <cuda_runtime.h>
#include <cuda_bf16.h>
#include <cstdint>

#define NN     16384
#define INF    256
#define OUTF   128
#define MAXNNZ 2048

// HW = H @ W^T (16384 x 128 fp32 = 8 MB, L2-resident)
__device__ float g_HW[NN * OUTF];

// ---------------------------------------------------------------------------
// HMMA helpers (sm_80-era mma.sync -- valid on sm_103 base target)
// ---------------------------------------------------------------------------
__device__ __forceinline__ void mma_bf16(float& c0, float& c1, float& c2, float& c3,
                                         uint32_t a0, uint32_t a1, uint32_t a2, uint32_t a3,
                                         uint32_t b0, uint32_t b1) {
    asm volatile(
        "mma.sync.aligned.m16n8k16.row.col.f32.bf16.bf16.f32 "
        "{%0,%1,%2,%3}, {%4,%5,%6,%7}, {%8,%9}, {%0,%1,%2,%3};"
        : "+f"(c0), "+f"(c1), "+f"(c2), "+f"(c3)
        : "r"(a0), "r"(a1), "r"(a2), "r"(a3), "r"(b0), "r"(b1));
}

__device__ __forceinline__ uint32_t bf16pair(float lo_elem, float hi_elem) {
    __nv_bfloat162 t = __floats2bfloat162_rn(lo_elem, hi_elem);  // .x = low 16b
    return *(uint32_t*)&t;
}
__device__ __forceinline__ void split2(float v, float& hi, float& lo) {
    __nv_bfloat16 h = __float2bfloat16_rn(v);
    hi = __bfloat162float(h);
    lo = v - hi;
}

// b-frag table: per n-row, 68 uint4 (16 ks x 4 q, padded 64 -> 68).
// n-stride = 272 words; 272 mod 32 == 16 -> LDS.128 phases conflict-free.
#define NSTRIDE_Q 68   // uint4 per n row

// ===========================================================================
// Kernel 1: g_HW = H @ W^T via mma.sync bf16 3-product split.
// 64 CTAs x 256 H-rows (two sequential 128-row tiles; W staged ONCE).
// Only 64 SMs carry the big-smem blocker -> aggregate's first wave gets
// 84 free SMs during the overlap window. PDL-triggers at entry.
// ===========================================================================
__global__ __launch_bounds__(256) void hw_mma(const float* __restrict__ H,
                                              const float* __restrict__ W) {
#if __CUDA_ARCH__ >= 900
    cudaTriggerProgrammaticLaunchCompletion();
#endif
    extern __shared__ uint4 wsq[];                 // [128][NSTRIDE_Q]

    const int tid  = threadIdx.x;
    const int w    = tid >> 5;
    const int lane = tid & 31;

    // ---- stage W once: (n, ks, q) -> {hi(k2),hi(k2+4),lo(k2),lo(k2+4)} ----
#pragma unroll
    for (int i = 0; i < (OUTF * 16 * 4) / 256; i++) {    // 32 uint4 / thread
        int idx = i * 256 + tid;                          // [0, 8192)
        int n   = idx >> 6;
        int ks  = (idx >> 2) & 15;
        int q   = idx & 3;
        int k2  = ks * 8 + q;
        float2 e0 = *(const float2*)&W[(size_t)n * INF + k2 * 2];
        float2 e1 = *(const float2*)&W[(size_t)n * INF + (k2 + 4) * 2];
        float h0, l0, h1, l1, h2, l2, h3, l3;
        split2(e0.x, h0, l0); split2(e0.y, h1, l1);
        split2(e1.x, h2, l2); split2(e1.y, h3, l3);
        uint4 v;
        v.x = bf16pair(h0, h1);   // bh0
        v.y = bf16pair(h2, h3);   // bh1
        v.z = bf16pair(l0, l1);   // bl0
        v.w = bf16pair(l2, l3);   // bl1
        wsq[n * NSTRIDE_Q + ks * 4 + q] = v;
    }
    __syncthreads();

    for (int tile = 0; tile < 2; tile++) {
        const int row0 = blockIdx.x * 256 + tile * 128;

        float acc[16][4];
#pragma unroll
        for (int nf = 0; nf < 16; nf++)
#pragma unroll
            for (int j = 0; j < 4; j++) acc[nf][j] = 0.f;

        const int ra = row0 + w * 16 + (lane >> 2);    // A rows: ra, ra+8
        const int kc = (lane & 3) * 2;

#pragma unroll
        for (int ks = 0; ks < 16; ks++) {
            const int k0 = ks * 16 + kc;
            float2 xa = *(const float2*)&H[(size_t)ra * INF + k0];
            float2 xb = *(const float2*)&H[(size_t)ra * INF + k0 + 8];
            float2 xc = *(const float2*)&H[(size_t)(ra + 8) * INF + k0];
            float2 xd = *(const float2*)&H[(size_t)(ra + 8) * INF + k0 + 8];

            float h0, l0, h1, l1;
            uint32_t ah[4], al[4];
            split2(xa.x, h0, l0); split2(xa.y, h1, l1);
            ah[0] = bf16pair(h0, h1); al[0] = bf16pair(l0, l1);
            split2(xc.x, h0, l0); split2(xc.y, h1, l1);
            ah[1] = bf16pair(h0, h1); al[1] = bf16pair(l0, l1);
            split2(xb.x, h0, l0); split2(xb.y, h1, l1);
            ah[2] = bf16pair(h0, h1); al[2] = bf16pair(l0, l1);
            split2(xd.x, h0, l0); split2(xd.y, h1, l1);
            ah[3] = bf16pair(h0, h1); al[3] = bf16pair(l0, l1);

            const int qoff = ks * 4 + (lane & 3);
#pragma unroll
            for (int nf = 0; nf < 16; nf++) {
                const int n = nf * 8 + (lane >> 2);
                uint4 b = wsq[n * NSTRIDE_Q + qoff];   // one LDS.128
                mma_bf16(acc[nf][0], acc[nf][1], acc[nf][2], acc[nf][3],
                         ah[0], ah[1], ah[2], ah[3], b.x, b.y);   // hi*hi
                mma_bf16(acc[nf][0], acc[nf][1], acc[nf][2], acc[nf][3],
                         ah[0], ah[1], ah[2], ah[3], b.z, b.w);   // hi*lo
                mma_bf16(acc[nf][0], acc[nf][1], acc[nf][2], acc[nf][3],
                         al[0], al[1], al[2], al[3], b.x, b.y);   // lo*hi
            }
        }

        const int r0 = row0 + w * 16 + (lane >> 2);
#pragma unroll
        for (int nf = 0; nf < 16; nf++) {
            const int c0 = nf * 8 + (lane & 3) * 2;
            *(float2*)&g_HW[(size_t)r0 * OUTF + c0]       = make_float2(acc[nf][0], acc[nf][1]);
            *(float2*)&g_HW[(size_t)(r0 + 8) * OUTF + c0] = make_float2(acc[nf][2], acc[nf][3]);
        }
    }
}

// ===========================================================================
// Kernel 2: R1 aggregate + grid-dependency sync AFTER the A-scan (proven).
// ===========================================================================
__global__ __launch_bounds__(256) void aggregate(const float* __restrict__ A,
                                                 float* __restrict__ out) {
    __shared__ int   s_idx[MAXNNZ];
    __shared__ int   s_cnt;
    __shared__ float s_red[OUTF];

    const int tid = threadIdx.x;
    const size_t row = blockIdx.x;

    if (tid == 0) s_cnt = 0;
    __syncthreads();

    const float4* Arow = (const float4*)(A + row * NN);
#pragma unroll
    for (int it = 0; it < NN / (256 * 4); it++) {
        int q = it * 256 + tid;
        float4 v = __ldcs(&Arow[q]);
        int base = q * 4;
        if (v.x != 0.f) { int p = atomicAdd(&s_cnt, 1); if (p < MAXNNZ) s_idx[p] = base;     }
        if (v.y != 0.f) { int p = atomicAdd(&s_cnt, 1); if (p < MAXNNZ) s_idx[p] = base + 1; }
        if (v.z != 0.f) { int p = atomicAdd(&s_cnt, 1); if (p < MAXNNZ) s_idx[p] = base + 2; }
        if (v.w != 0.f) { int p = atomicAdd(&s_cnt, 1); if (p < MAXNNZ) s_idx[p] = base + 3; }
    }
    __syncthreads();

#if __CUDA_ARCH__ >= 900
    cudaGridDependencySynchronize();   // g_HW ready past this point
#endif

    const int cnt = s_cnt;
    const int lim = cnt < MAXNNZ ? cnt : MAXNNZ;
    const int c = tid & 127;
    const int h = tid >> 7;

    float acc = 0.f;
    for (int k = h; k < lim; k += 2)
        acc += g_HW[(size_t)s_idx[k] * OUTF + c];

    if (h == 1) s_red[c] = acc;
    __syncthreads();
    if (h == 0) {
        float total = acc + s_red[c];
        out[row * OUTF + c] = total / (float)(cnt + 1);
    }
}

extern "C" void kernel_launch(void* const* d_in, const int* in_sizes, int n_in,
                              void* d_out, int out_size) {
    const float* A = (const float*)d_in[0];   // [16384, 16384]
    const float* H = (const float*)d_in[1];   // [16384, 256]
    const float* W = (const float*)d_in[2];   // [128, 256]
    float* out = (float*)d_out;               // [16384, 128]
    (void)in_sizes; (void)n_in; (void)out_size;

    const int wsm = OUTF * NSTRIDE_Q * 16;    // 139264 B dynamic smem
    cudaFuncSetAttribute(hw_mma, cudaFuncAttributeMaxDynamicSharedMemorySize, wsm);
    hw_mma<<<NN / 256, 256, wsm>>>(H, W);     // 64 CTAs

    // Programmatic Dependent Launch: aggregate begins while hw_mma runs;
    // in-kernel cudaGridDependencySynchronize() gates g_HW consumption.
    cudaLaunchConfig_t cfg = {};
    cfg.gridDim  = dim3(NN, 1, 1);
    cfg.blockDim = dim3(256, 1, 1);
    cfg.dynamicSmemBytes = 0;
    cudaLaunchAttribute attr[1];
    attr[0].id = cudaLaunchAttributeProgrammaticStreamSerialization;
    attr[0].val.programmaticStreamSerializationAllowed = 1;
    cfg.attrs    = attr;
    cfg.numAttrs = 1;
    cudaLaunchKernelEx(&cfg, aggregate, A, out);
}

// round 13
// speedup vs baseline: 1.0347x; 1.0347x over previous
#include <cuda_runtime.h>
#include <cuda_bf16.h>
#include <cstdint>

#define NN     16384
#define INF    256
#define OUTF   128
#define MAXNNZ 2048

// HW = H @ W^T (16384 x 128 fp32 = 8 MB, L2-resident)
__device__ float g_HW[NN * OUTF];

// ---------------------------------------------------------------------------
// HMMA helpers (sm_80-era mma.sync -- valid on sm_103 base target)
// ---------------------------------------------------------------------------
__device__ __forceinline__ void mma_bf16(float& c0, float& c1, float& c2, float& c3,
                                         uint32_t a0, uint32_t a1, uint32_t a2, uint32_t a3,
                                         uint32_t b0, uint32_t b1) {
    asm volatile(
        "mma.sync.aligned.m16n8k16.row.col.f32.bf16.bf16.f32 "
        "{%0,%1,%2,%3}, {%4,%5,%6,%7}, {%8,%9}, {%0,%1,%2,%3};"
        : "+f"(c0), "+f"(c1), "+f"(c2), "+f"(c3)
        : "r"(a0), "r"(a1), "r"(a2), "r"(a3), "r"(b0), "r"(b1));
}

__device__ __forceinline__ uint32_t bf16pair(float lo_elem, float hi_elem) {
    __nv_bfloat162 t = __floats2bfloat162_rn(lo_elem, hi_elem);  // .x = low 16b
    return *(uint32_t*)&t;
}
__device__ __forceinline__ void split2(float v, float& hi, float& lo) {
    __nv_bfloat16 h = __float2bfloat16_rn(v);
    hi = __bfloat162float(h);
    lo = v - hi;
}

// b-frag table: per n-row, 68 uint4 (16 ks x 4 q, padded 64 -> 68).
// n-stride = 272 words; 272 mod 32 == 16 -> LDS.128 phases conflict-free.
#define NSTRIDE_Q 68   // uint4 per n row

// ===========================================================================
// Kernel 1: g_HW = H @ W^T via mma.sync bf16 3-product split (R11 config:
// 128 CTAs x 128 rows -- the proven overlap shape). PDL-triggers at entry.
// ===========================================================================
__global__ __launch_bounds__(256) void hw_mma(const float* __restrict__ H,
                                              const float* __restrict__ W) {
#if __CUDA_ARCH__ >= 900
    cudaTriggerProgrammaticLaunchCompletion();
#endif
    extern __shared__ uint4 wsq[];                 // [128][NSTRIDE_Q]

    const int tid  = threadIdx.x;
    const int w    = tid >> 5;
    const int lane = tid & 31;
    const int row0 = blockIdx.x * 128;

    // ---- stage W: (n, ks, q) -> {hi(k2),hi(k2+4),lo(k2),lo(k2+4)} ----
#pragma unroll
    for (int i = 0; i < (OUTF * 16 * 4) / 256; i++) {    // 32 uint4 / thread
        int idx = i * 256 + tid;                          // [0, 8192)
        int n   = idx >> 6;
        int ks  = (idx >> 2) & 15;
        int q   = idx & 3;
        int k2  = ks * 8 + q;
        float2 e0 = *(const float2*)&W[(size_t)n * INF + k2 * 2];
        float2 e1 = *(const float2*)&W[(size_t)n * INF + (k2 + 4) * 2];
        float h0, l0, h1, l1, h2, l2, h3, l3;
        split2(e0.x, h0, l0); split2(e0.y, h1, l1);
        split2(e1.x, h2, l2); split2(e1.y, h3, l3);
        uint4 v;
        v.x = bf16pair(h0, h1);   // bh0
        v.y = bf16pair(h2, h3);   // bh1
        v.z = bf16pair(l0, l1);   // bl0
        v.w = bf16pair(l2, l3);   // bl1
        wsq[n * NSTRIDE_Q + ks * 4 + q] = v;
    }
    __syncthreads();

    float acc[16][4];
#pragma unroll
    for (int nf = 0; nf < 16; nf++)
#pragma unroll
        for (int j = 0; j < 4; j++) acc[nf][j] = 0.f;

    const int ra = row0 + w * 16 + (lane >> 2);    // A rows: ra, ra+8
    const int kc = (lane & 3) * 2;

#pragma unroll
    for (int ks = 0; ks < 16; ks++) {
        const int k0 = ks * 16 + kc;
        float2 xa = *(const float2*)&H[(size_t)ra * INF + k0];
        float2 xb = *(const float2*)&H[(size_t)ra * INF + k0 + 8];
        float2 xc = *(const float2*)&H[(size_t)(ra + 8) * INF + k0];
        float2 xd = *(const float2*)&H[(size_t)(ra + 8) * INF + k0 + 8];

        float h0, l0, h1, l1;
        uint32_t ah[4], al[4];
        split2(xa.x, h0, l0); split2(xa.y, h1, l1);
        ah[0] = bf16pair(h0, h1); al[0] = bf16pair(l0, l1);
        split2(xc.x, h0, l0); split2(xc.y, h1, l1);
        ah[1] = bf16pair(h0, h1); al[1] = bf16pair(l0, l1);
        split2(xb.x, h0, l0); split2(xb.y, h1, l1);
        ah[2] = bf16pair(h0, h1); al[2] = bf16pair(l0, l1);
        split2(xd.x, h0, l0); split2(xd.y, h1, l1);
        ah[3] = bf16pair(h0, h1); al[3] = bf16pair(l0, l1);

        const int qoff = ks * 4 + (lane & 3);
#pragma unroll
        for (int nf = 0; nf < 16; nf++) {
            const int n = nf * 8 + (lane >> 2);
            uint4 b = wsq[n * NSTRIDE_Q + qoff];   // one LDS.128
            mma_bf16(acc[nf][0], acc[nf][1], acc[nf][2], acc[nf][3],
                     ah[0], ah[1], ah[2], ah[3], b.x, b.y);   // hi*hi
            mma_bf16(acc[nf][0], acc[nf][1], acc[nf][2], acc[nf][3],
                     ah[0], ah[1], ah[2], ah[3], b.z, b.w);   // hi*lo
            mma_bf16(acc[nf][0], acc[nf][1], acc[nf][2], acc[nf][3],
                     al[0], al[1], al[2], al[3], b.x, b.y);   // lo*hi
        }
    }

    const int r0 = row0 + w * 16 + (lane >> 2);
#pragma unroll
    for (int nf = 0; nf < 16; nf++) {
        const int c0 = nf * 8 + (lane & 3) * 2;
        *(float2*)&g_HW[(size_t)r0 * OUTF + c0]       = make_float2(acc[nf][0], acc[nf][1]);
        *(float2*)&g_HW[(size_t)(r0 + 8) * OUTF + c0] = make_float2(acc[nf][2], acc[nf][3]);
    }
}

// ===========================================================================
// Kernel 2: aggregate with depth-2 batched scan loads (MLP x2) + PDL sync
// after the scan. launch_bounds(256, 6): reg cap 42 -> no spill, occ 6.
// ===========================================================================
__global__ __launch_bounds__(256, 6) void aggregate(const float* __restrict__ A,
                                                    float* __restrict__ out) {
    __shared__ int   s_idx[MAXNNZ];
    __shared__ int   s_cnt;
    __shared__ float s_red[OUTF];

    const int tid = threadIdx.x;
    const size_t row = blockIdx.x;

    if (tid == 0) s_cnt = 0;
    __syncthreads();

    const float4* Arow = (const float4*)(A + row * NN);
#pragma unroll
    for (int it = 0; it < NN / (256 * 4 * 2); it++) {   // 8 iters, 2 loads each
        const int q0 = it * 512 + tid;
        float4 v0 = __ldcs(&Arow[q0]);          // two independent LDG.128s
        float4 v1 = __ldcs(&Arow[q0 + 256]);    // front-batched -> MLP=2
#define EMIT(vv, qq)                                                           \
        do {                                                                   \
            int base = (qq) * 4;                                               \
            if ((vv).x != 0.f) { int p = atomicAdd(&s_cnt, 1); if (p < MAXNNZ) s_idx[p] = base;     } \
            if ((vv).y != 0.f) { int p = atomicAdd(&s_cnt, 1); if (p < MAXNNZ) s_idx[p] = base + 1; } \
            if ((vv).z != 0.f) { int p = atomicAdd(&s_cnt, 1); if (p < MAXNNZ) s_idx[p] = base + 2; } \
            if ((vv).w != 0.f) { int p = atomicAdd(&s_cnt, 1); if (p < MAXNNZ) s_idx[p] = base + 3; } \
        } while (0)
        EMIT(v0, q0);
        EMIT(v1, q0 + 256);
#undef EMIT
    }
    __syncthreads();

#if __CUDA_ARCH__ >= 900
    cudaGridDependencySynchronize();   // g_HW ready past this point
#endif

    const int cnt = s_cnt;
    const int lim = cnt < MAXNNZ ? cnt : MAXNNZ;
    const int c = tid & 127;
    const int h = tid >> 7;

    float acc = 0.f;
    for (int k = h; k < lim; k += 2)
        acc += g_HW[(size_t)s_idx[k] * OUTF + c];

    if (h == 1) s_red[c] = acc;
    __syncthreads();
    if (h == 0) {
        float total = acc + s_red[c];
        out[row * OUTF + c] = total / (float)(cnt + 1);
    }
}

extern "C" void kernel_launch(void* const* d_in, const int* in_sizes, int n_in,
                              void* d_out, int out_size) {
    const float* A = (const float*)d_in[0];   // [16384, 16384]
    const float* H = (const float*)d_in[1];   // [16384, 256]
    const float* W = (const float*)d_in[2];   // [128, 256]
    float* out = (float*)d_out;               // [16384, 128]
    (void)in_sizes; (void)n_in; (void)out_size;

    const int wsm = OUTF * NSTRIDE_Q * 16;    // 139264 B dynamic smem
    cudaFuncSetAttribute(hw_mma, cudaFuncAttributeMaxDynamicSharedMemorySize, wsm);
    hw_mma<<<NN / 128, 256, wsm>>>(H, W);     // 128 CTAs (R11 proven shape)

    // Programmatic Dependent Launch: aggregate begins while hw_mma runs;
    // in-kernel cudaGridDependencySynchronize() gates g_HW consumption.
    cudaLaunchConfig_t cfg = {};
    cfg.gridDim  = dim3(NN, 1, 1);
    cfg.blockDim = dim3(256, 1, 1);
    cfg.dynamicSmemBytes = 0;
    cudaLaunchAttribute attr[1];
    attr[0].id = cudaLaunchAttributeProgrammaticStreamSerialization;
    attr[0].val.programmaticStreamSerializationAllowed = 1;
    cfg.attrs    = attr;
    cfg.numAttrs = 1;
    cudaLaunchKernelEx(&cfg, aggregate, A, out);
}